// round 6
// baseline (speedup 1.0000x reference)
#include <cuda_runtime.h>
#include <cuda_fp16.h>

#define C_DIM 2048
#define B_DIM 64
#define I_DIM 8
#define U_DIM 32
#define D_DIM 16
#define UD    512
#define NBLK  148
#define NTH   1024

typedef unsigned long long u64;

// ---- scratch (static __device__: allocation-free) ----
__device__ float g_xt[C_DIM * B_DIM * I_DIM];     // x transposed: [c][b][i]
__device__ float g_spart[NBLK * B_DIM * UD];      // per-block s partials
__device__ float g_v[B_DIM * UD];                 // squashed v
__device__ float g_b[C_DIM * U_DIM];              // routing logits

__device__ __forceinline__ u64 mul2(u64 a, u64 b) {
    u64 r; asm("mul.rn.f32x2 %0, %1, %2;" : "=l"(r) : "l"(a), "l"(b)); return r;
}
__device__ __forceinline__ u64 fma2(u64 a, u64 b, u64 c) {
    u64 r; asm("fma.rn.f32x2 %0, %1, %2, %3;" : "=l"(r) : "l"(a), "l"(b), "l"(c)); return r;
}
__device__ __forceinline__ float hadd2(u64 a) {
    float lo, hi; asm("mov.b64 {%0,%1}, %2;" : "=f"(lo), "=f"(hi) : "l"(a));
    return lo + hi;
}
// volatile loads: pin in place; stop ptxas hoisting/batching (reg-pressure bomb)
__device__ __forceinline__ float ldg_f(const float* p) {
    float r; asm volatile("ld.global.nc.f32 %0, [%1];" : "=f"(r) : "l"(p)); return r;
}
__device__ __forceinline__ void ldg_2u64(const float* p, u64& a, u64& b) {
    asm volatile("ld.global.nc.v2.u64 {%0,%1}, [%2];" : "=l"(a), "=l"(b) : "l"(p));
}

__device__ __forceinline__ float dot8(ulonglong2 wa, ulonglong2 wb,
                                      u64 x0, u64 x1, u64 x2, u64 x3) {
    u64 acc = mul2(wa.x, x0);
    acc = fma2(wa.y, x1, acc);
    acc = fma2(wb.x, x2, acc);
    acc = fma2(wb.y, x3, acc);
    return hadd2(acc);
}

// x (B,I,C) -> g_xt[c][b][i]
__global__ void k_transpose(const float* __restrict__ x) {
    int idx = blockIdx.x * blockDim.x + threadIdx.x;
    if (idx >= C_DIM * B_DIM * I_DIM) return;
    int c = idx >> 9;
    int r = idx & 511;
    int b = r >> 3;
    int i = r & 7;
    g_xt[idx] = x[(b * I_DIM + i) * C_DIM + c];
}

// ---------------------------------------------------------------------------
// Fused routing pass. 32 warps = 8 ud-groups (wu) x 4 b-groups (wb).
// Lane owns ud = wu*64 + k*32 + lane (k=0,1)  ->  u = wu*4 + 2k + (lane>>4).
// Warp owns batches b = wb*16 + 0..15.  sacc[2][16] = 32 regs -> <=64 regs,
// 50% occupancy (8 warps/SMSP).
// PASS==0: cij = 1/32, barrier-free.
// PASS>0 : stash u_hat as half2 (64 KB), dot with v (fp32), ONE barrier per c,
//          softmax recomputed redundantly per warp from ping-pong red_sm.
// ---------------------------------------------------------------------------
template <int PASS>
__global__ void __launch_bounds__(NTH, 1) k_pass(const float* __restrict__ W) {
    extern __shared__ __half2 stash[];         // [16][NTH] : 64 KB (PASS>0)
    __shared__ float red_sm[2][4][32];         // [c-parity][wb][u]

    const int tid  = threadIdx.x;
    const int w    = tid >> 5;
    const int lane = tid & 31;
    const int wu   = w & 7;
    const int wb   = w >> 3;
    const int hw   = lane >> 4;
    const int ud0  = wu * 64 + lane;

    float sacc[2][16];
#pragma unroll
    for (int k = 0; k < 2; k++)
#pragma unroll
        for (int r = 0; r < 16; r++) sacc[k][r] = 0.f;

    const int cbeg = (blockIdx.x * C_DIM) / NBLK;
    const int cend = ((blockIdx.x + 1) * C_DIM) / NBLK;
    int par = 0;

    for (int c = cbeg; c < cend; c++) {
        const ulonglong2* Wp = (const ulonglong2*)(W + (size_t)c * (UD * I_DIM));
        ulonglong2 wA0 = Wp[2 * ud0],        wB0 = Wp[2 * ud0 + 1];
        ulonglong2 wA1 = Wp[2 * (ud0 + 32)], wB1 = Wp[2 * (ud0 + 32) + 1];
        if (c + 1 < cend)   // pull next c's W tile into L2 (1024 thr x 16B = 16KB)
            asm volatile("prefetch.global.L2 [%0];"
                         :: "l"(W + (size_t)(c + 1) * (UD * I_DIM) + tid * 4));

        const float* xc = g_xt + c * (B_DIM * I_DIM) + wb * 128;   // 16 b x 8 i
        const float* vb = g_v + (wb * 16) * UD + ud0;
        float dp0 = 0.f, dp1 = 0.f;
        float bprev = (PASS == 2) ? g_b[c * U_DIM + lane] : 0.f;   // pre-barrier

#pragma unroll
        for (int r = 0; r < 16; r++) {
            u64 x0, x1, x2, x3;
            ldg_2u64(xc + r * 8,     x0, x1);    // warp-uniform, L1-hot
            ldg_2u64(xc + r * 8 + 4, x2, x3);
            float u0 = dot8(wA0, wB0, x0, x1, x2, x3);
            float u1 = dot8(wA1, wB1, x0, x1, x2, x3);
            if (PASS > 0) {
                stash[r * NTH + tid] = __floats2half2_rn(u0, u1);
                float v0 = ldg_f(vb + r * UD);
                float v1 = ldg_f(vb + r * UD + 32);
                dp0 = fmaf(u0, v0, dp0);
                dp1 = fmaf(u1, v1, dp1);
            } else {
                sacc[0][r] += u0;
                sacc[1][r] += u1;
            }
        }

        if (PASS > 0) {
            // reduce dp over d (16-lane segments); lanes 0/16 hold u-sums
#pragma unroll
            for (int off = 8; off; off >>= 1) {
                dp0 += __shfl_down_sync(0xffffffffu, dp0, off, 16);
                dp1 += __shfl_down_sync(0xffffffffu, dp1, off, 16);
            }
            if ((lane & 15) == 0) {
                red_sm[par][wb][wu * 4 + hw]     = dp0;   // u = wu*4 + 0 + hw
                red_sm[par][wb][wu * 4 + 2 + hw] = dp1;   // u = wu*4 + 2 + hw
            }
            __syncthreads();                    // the ONLY barrier this c

            // redundant per-warp softmax over u (lane = u)
            float dv = red_sm[par][0][lane] + red_sm[par][1][lane] +
                       red_sm[par][2][lane] + red_sm[par][3][lane];
            float bv = dv * (1.0f / 64.0f) + bprev;
            if (PASS == 1 && w == 0) g_b[c * U_DIM + lane] = bv;
            float m = bv;
#pragma unroll
            for (int off = 16; off; off >>= 1)
                m = fmaxf(m, __shfl_xor_sync(0xffffffffu, m, off));
            float e = __expf(bv - m);
            float ssum = e;
#pragma unroll
            for (int off = 16; off; off >>= 1)
                ssum += __shfl_xor_sync(0xffffffffu, ssum, off);
            float cij_lane = e / ssum;
            float cij0 = __shfl_sync(0xffffffffu, cij_lane, wu * 4 + hw);
            float cij1 = __shfl_sync(0xffffffffu, cij_lane, wu * 4 + 2 + hw);

            // phase B: accumulate s from self-stashed u_hat (no sync needed)
#pragma unroll
            for (int r = 0; r < 16; r++) {
                float2 q = __half22float2(stash[r * NTH + tid]);
                sacc[0][r] = fmaf(cij0, q.x, sacc[0][r]);
                sacc[1][r] = fmaf(cij1, q.y, sacc[1][r]);
            }
            par ^= 1;
        }
    }

    const float scale = (PASS == 0) ? (1.0f / 32.0f) : 1.0f;
    float* sp = g_spart + (size_t)blockIdx.x * (B_DIM * UD);
#pragma unroll
    for (int r = 0; r < 16; r++)
#pragma unroll
        for (int k = 0; k < 2; k++)
            sp[(wb * 16 + r) * UD + ud0 + k * 32] = sacc[k][r] * scale;
}

// Reduce per-block s partials, apply squash (mag over U axis — reference quirk).
__global__ void k_redsquash(float* __restrict__ dout, int final_out) {
    __shared__ float sq_sm[UD];
    __shared__ float r_sm[D_DIM];
    int b = blockIdx.x;
    int ud = threadIdx.x;      // 512 threads
    float val = 0.f;
    const float* sp = g_spart + b * UD + ud;
#pragma unroll 4
    for (int p = 0; p < NBLK; p++) val += sp[(size_t)p * (B_DIM * UD)];
    sq_sm[ud] = val * val;
    __syncthreads();
    if (ud < D_DIM) {
        float msq = 0.f;
#pragma unroll
        for (int u = 0; u < U_DIM; u++) msq += sq_sm[u * D_DIM + ud];
        r_sm[ud] = sqrtf(msq) / (1.0f + msq);   // mag_sq/((1+mag_sq)*mag)
    }
    __syncthreads();
    float v = val * r_sm[ud & 15];
    float* dst = final_out ? dout : g_v;
    dst[b * UD + ud] = v;
}

extern "C" void kernel_launch(void* const* d_in, const int* in_sizes, int n_in,
                              void* d_out, int out_size) {
    const float* x = (const float*)d_in[0];
    const float* W = (const float*)d_in[1];
    if (n_in >= 2 && in_sizes[0] == C_DIM * U_DIM * D_DIM * I_DIM) {
        const float* t = x; x = W; W = t;
    }
    float* out = (float*)d_out;

    const int STASH = 16 * NTH * (int)sizeof(__half2);   // 64 KB
    cudaFuncSetAttribute(k_pass<1>, cudaFuncAttributeMaxDynamicSharedMemorySize, STASH);
    cudaFuncSetAttribute(k_pass<2>, cudaFuncAttributeMaxDynamicSharedMemorySize, STASH);

    k_transpose<<<(C_DIM * B_DIM * I_DIM + 255) / 256, 256>>>(x);

    // iteration 1: uniform cij -> s1 -> v1
    k_pass<0><<<NBLK, NTH>>>(W);
    k_redsquash<<<B_DIM, UD>>>(out, 0);

    // iteration 2: delta(v1), b = delta, softmax -> s2 -> v2
    k_pass<1><<<NBLK, NTH, STASH>>>(W);
    k_redsquash<<<B_DIM, UD>>>(out, 0);

    // iteration 3: delta(v2), b += delta, softmax -> s3 -> v3 (output)
    k_pass<2><<<NBLK, NTH, STASH>>>(W);
    k_redsquash<<<B_DIM, UD>>>(out, 1);
}

// round 7
// speedup vs baseline: 1.5429x; 1.5429x over previous
#include <cuda_runtime.h>
#include <cuda_fp16.h>

#define C_DIM 2048
#define B_DIM 64
#define I_DIM 8
#define U_DIM 32
#define D_DIM 16
#define UD    512
#define NBLK  148
#define NTH   1024

typedef unsigned long long u64;
typedef unsigned int u32;

// ---- scratch (static __device__: allocation-free) ----
__device__ float g_xt[C_DIM * B_DIM * I_DIM];     // x transposed: [c][b][i]
__device__ float g_spart[NBLK * B_DIM * UD];      // per-block s partials
__device__ float g_v[B_DIM * UD];                 // squashed v
__device__ float g_b[C_DIM * U_DIM];              // routing logits

__device__ __forceinline__ u64 mul2(u64 a, u64 b) {
    u64 r; asm("mul.rn.f32x2 %0, %1, %2;" : "=l"(r) : "l"(a), "l"(b)); return r;
}
__device__ __forceinline__ u64 fma2(u64 a, u64 b, u64 c) {
    u64 r; asm("fma.rn.f32x2 %0, %1, %2, %3;" : "=l"(r) : "l"(a), "l"(b), "l"(c)); return r;
}
__device__ __forceinline__ float hadd2(u64 a) {
    float lo, hi; asm("mov.b64 {%0,%1}, %2;" : "=f"(lo), "=f"(hi) : "l"(a));
    return lo + hi;
}
__device__ __forceinline__ float ldg_f(const float* p) {
    float r; asm volatile("ld.global.nc.f32 %0, [%1];" : "=f"(r) : "l"(p)); return r;
}
__device__ __forceinline__ u32 smem_u32(const void* p) {
    return (u32)__cvta_generic_to_shared(p);
}
__device__ __forceinline__ void cp16(u32 dst, const void* src) {
    asm volatile("cp.async.cg.shared.global [%0], [%1], 16;" :: "r"(dst), "l"(src));
}
#define CP_COMMIT() asm volatile("cp.async.commit_group;")
#define CP_WAIT0()  asm volatile("cp.async.wait_group 0;" ::: "memory")
// W row load from smem (non-volatile: may issue early)
__device__ __forceinline__ void lds_2u64(u32 a, u64& x, u64& y) {
    asm("ld.shared.v2.u64 {%0,%1}, [%2];" : "=l"(x), "=l"(y) : "r"(a));
}
// x load from smem (volatile: stop hoist-all / reg bomb)
__device__ __forceinline__ void lds_2u64v(u32 a, u64& x, u64& y) {
    asm volatile("ld.shared.v2.u64 {%0,%1}, [%2];" : "=l"(x), "=l"(y) : "r"(a));
}
__device__ __forceinline__ float dot8(u64 wa0, u64 wa1, u64 wb0, u64 wb1,
                                      u64 x0, u64 x1, u64 x2, u64 x3) {
    u64 acc = mul2(wa0, x0);
    acc = fma2(wa1, x1, acc);
    acc = fma2(wb0, x2, acc);
    acc = fma2(wb1, x3, acc);
    return hadd2(acc);
}

// x (B,I,C) -> g_xt[c][b][i]
__global__ void k_transpose(const float* __restrict__ x) {
    int idx = blockIdx.x * blockDim.x + threadIdx.x;
    if (idx >= C_DIM * B_DIM * I_DIM) return;
    int c = idx >> 9;
    int r = idx & 511;
    int b = r >> 3;
    int i = r & 7;
    g_xt[idx] = x[(b * I_DIM + i) * C_DIM + c];
}

// ---------------------------------------------------------------------------
// Fused routing pass, cp.async software-pipelined.
// 32 warps = 16 ud-groups (wu) x 2 b-groups (wb).
// Lane owns ud = wu*32 + lane (u = wu*2 + (lane>>4), d = lane&15),
// batches b = wb*32 + 0..31.  sacc[32] regs, W row = 8 regs -> ~60 regs total.
// W_c (16KB) + x_c (2KB) staged in smem one c ahead (double-buffered).
// PASS>0: stash u_hat as packed half (uint4 STS/LDS.128), softmax redundant
// per warp off ping-pong red_sm; ONE barrier per c (= pipeline boundary).
// ---------------------------------------------------------------------------
template <int PASS>
__global__ void __launch_bounds__(NTH, 1) k_pass(const float* __restrict__ W) {
    extern __shared__ char dyn[];
    // layout: Wbuf[2][16384] | xbuf[2][2048] | stash[65536 (PASS>0)]
    const u32 wbase  = smem_u32(dyn);
    const u32 xbase  = wbase + 32768;
    const u32 stbase = xbase + 4096;
    __shared__ float red_sm[2][2][32];

    const int tid  = threadIdx.x;
    const int w    = tid >> 5;
    const int lane = tid & 31;
    const int wu   = w & 15;
    const int wb   = w >> 4;
    const int hw   = lane >> 4;
    const int ud   = wu * 32 + lane;

    float sacc[32];
#pragma unroll
    for (int r = 0; r < 32; r++) sacc[r] = 0.f;

    const int cbeg = (blockIdx.x * C_DIM) / NBLK;
    const int cend = ((blockIdx.x + 1) * C_DIM) / NBLK;
    int par = 0;

    // prologue: stage first c
    cp16(wbase + tid * 16, (const char*)(W + (size_t)cbeg * 4096) + tid * 16);
    if (tid < 128)
        cp16(xbase + tid * 16, (const char*)(g_xt + cbeg * 512) + tid * 16);
    CP_COMMIT();
    CP_WAIT0();
    __syncthreads();

    for (int c = cbeg; c < cend; c++) {
        // issue next c's staging into the other buffer (overlaps phase A)
        if (c + 1 < cend) {
            const int np = par ^ 1;
            cp16(wbase + np * 16384 + tid * 16,
                 (const char*)(W + (size_t)(c + 1) * 4096) + tid * 16);
            if (tid < 128)
                cp16(xbase + np * 2048 + tid * 16,
                     (const char*)(g_xt + (c + 1) * 512) + tid * 16);
        }
        CP_COMMIT();

        // this lane's W row (8 floats) from smem
        u64 wa0, wa1, wbb0, wbb1;
        lds_2u64(wbase + par * 16384 + ud * 32, wa0, wa1);
        lds_2u64(wbase + par * 16384 + ud * 32 + 16, wbb0, wbb1);

        float bprev = (PASS == 2) ? g_b[c * U_DIM + lane] : 0.f;
        const float* vb = g_v + (wb * 32) * UD + ud;
        const u32 xb = xbase + par * 2048 + wb * 1024;
        float dp = 0.f;

#pragma unroll
        for (int j = 0; j < 4; j++) {           // 8 batches per chunk
            u32 pk[4];
#pragma unroll
            for (int t2 = 0; t2 < 4; t2++) {    // 2 batches per step
                const int r = j * 8 + t2 * 2;
                u64 x0, x1, x2, x3, y0, y1, y2, y3;
                lds_2u64v(xb + r * 32,      x0, x1);
                lds_2u64v(xb + r * 32 + 16, x2, x3);
                lds_2u64v(xb + r * 32 + 32, y0, y1);
                lds_2u64v(xb + r * 32 + 48, y2, y3);
                float ua = dot8(wa0, wa1, wbb0, wbb1, x0, x1, x2, x3);
                float ub = dot8(wa0, wa1, wbb0, wbb1, y0, y1, y2, y3);
                if (PASS > 0) {
                    dp = fmaf(ua, ldg_f(vb + r * UD), dp);
                    dp = fmaf(ub, ldg_f(vb + (r + 1) * UD), dp);
                    __half2 h2 = __floats2half2_rn(ua, ub);
                    pk[t2] = *(u32*)&h2;
                } else {
                    sacc[r]     += ua;
                    sacc[r + 1] += ub;
                }
            }
            if (PASS > 0) {
                asm volatile("st.shared.v4.b32 [%0], {%1,%2,%3,%4};"
                             :: "r"(stbase + (j * NTH + tid) * 16),
                                "r"(pk[0]), "r"(pk[1]), "r"(pk[2]), "r"(pk[3]));
            }
        }

        if (PASS > 0) {
            // reduce dp over d (16-lane segments); lanes 0/16 hold u partials
#pragma unroll
            for (int off = 8; off; off >>= 1)
                dp += __shfl_down_sync(0xffffffffu, dp, off, 16);
            if ((lane & 15) == 0)
                red_sm[par][wb][wu * 2 + hw] = dp;
        }

        CP_WAIT0();                 // next c's operands landed
        __syncthreads();            // the ONLY barrier this c

        if (PASS > 0) {
            // redundant per-warp softmax over u (lane = u)
            float dv = red_sm[par][0][lane] + red_sm[par][1][lane];
            float bv = dv * (1.0f / 64.0f) + bprev;
            if (PASS == 1 && w == 0) g_b[c * U_DIM + lane] = bv;
            float m = bv;
#pragma unroll
            for (int off = 16; off; off >>= 1)
                m = fmaxf(m, __shfl_xor_sync(0xffffffffu, m, off));
            float e = __expf(bv - m);
            float ssum = e;
#pragma unroll
            for (int off = 16; off; off >>= 1)
                ssum += __shfl_xor_sync(0xffffffffu, ssum, off);
            float cij = __shfl_sync(0xffffffffu, e / ssum, wu * 2 + hw);

            // phase B: accumulate s from stash (self-written, no extra sync)
#pragma unroll
            for (int j = 0; j < 4; j++) {
                u32 q0, q1, q2, q3;
                asm volatile("ld.shared.v4.b32 {%0,%1,%2,%3}, [%4];"
                             : "=r"(q0), "=r"(q1), "=r"(q2), "=r"(q3)
                             : "r"(stbase + (j * NTH + tid) * 16));
                u32 qs[4] = {q0, q1, q2, q3};
#pragma unroll
                for (int t2 = 0; t2 < 4; t2++) {
                    float2 uv = __half22float2(*(__half2*)&qs[t2]);
                    sacc[j * 8 + t2 * 2]     = fmaf(cij, uv.x, sacc[j * 8 + t2 * 2]);
                    sacc[j * 8 + t2 * 2 + 1] = fmaf(cij, uv.y, sacc[j * 8 + t2 * 2 + 1]);
                }
            }
        }
        par ^= 1;
    }

    const float scale = (PASS == 0) ? (1.0f / 32.0f) : 1.0f;
    float* sp = g_spart + (size_t)blockIdx.x * (B_DIM * UD) + ud;
#pragma unroll
    for (int r = 0; r < 32; r++)
        sp[(wb * 32 + r) * UD] = sacc[r] * scale;
}

// Reduce per-block s partials, apply squash (mag over U axis — reference quirk).
__global__ void k_redsquash(float* __restrict__ dout, int final_out) {
    __shared__ float sq_sm[UD];
    __shared__ float r_sm[D_DIM];
    int b = blockIdx.x;
    int ud = threadIdx.x;      // 512 threads
    float val = 0.f;
    const float* sp = g_spart + b * UD + ud;
#pragma unroll 4
    for (int p = 0; p < NBLK; p++) val += sp[(size_t)p * (B_DIM * UD)];
    sq_sm[ud] = val * val;
    __syncthreads();
    if (ud < D_DIM) {
        float msq = 0.f;
#pragma unroll
        for (int u = 0; u < U_DIM; u++) msq += sq_sm[u * D_DIM + ud];
        r_sm[ud] = sqrtf(msq) / (1.0f + msq);   // mag_sq/((1+mag_sq)*mag)
    }
    __syncthreads();
    float v = val * r_sm[ud & 15];
    float* dst = final_out ? dout : g_v;
    dst[b * UD + ud] = v;
}

extern "C" void kernel_launch(void* const* d_in, const int* in_sizes, int n_in,
                              void* d_out, int out_size) {
    const float* x = (const float*)d_in[0];
    const float* W = (const float*)d_in[1];
    if (n_in >= 2 && in_sizes[0] == C_DIM * U_DIM * D_DIM * I_DIM) {
        const float* t = x; x = W; W = t;
    }
    float* out = (float*)d_out;

    const int SM0 = 32768 + 4096;            // W/x buffers only
    const int SM1 = 32768 + 4096 + 65536;    // + stash
    cudaFuncSetAttribute(k_pass<0>, cudaFuncAttributeMaxDynamicSharedMemorySize, SM0);
    cudaFuncSetAttribute(k_pass<1>, cudaFuncAttributeMaxDynamicSharedMemorySize, SM1);
    cudaFuncSetAttribute(k_pass<2>, cudaFuncAttributeMaxDynamicSharedMemorySize, SM1);

    k_transpose<<<(C_DIM * B_DIM * I_DIM + 255) / 256, 256>>>(x);

    // iteration 1: uniform cij -> s1 -> v1
    k_pass<0><<<NBLK, NTH, SM0>>>(W);
    k_redsquash<<<B_DIM, UD>>>(out, 0);

    // iteration 2: delta(v1), b = delta, softmax -> s2 -> v2
    k_pass<1><<<NBLK, NTH, SM1>>>(W);
    k_redsquash<<<B_DIM, UD>>>(out, 0);

    // iteration 3: delta(v2), b += delta, softmax -> s3 -> v3 (output)
    k_pass<2><<<NBLK, NTH, SM1>>>(W);
    k_redsquash<<<B_DIM, UD>>>(out, 1);
}

// round 8
// speedup vs baseline: 1.5543x; 1.0074x over previous
#include <cuda_runtime.h>
#include <cuda_fp16.h>

#define C_DIM 2048
#define B_DIM 64
#define I_DIM 8
#define U_DIM 32
#define D_DIM 16
#define UD    512
#define NBLK  148
#define NTH   1024

typedef unsigned long long u64;
typedef unsigned int u32;

// ---- scratch (static __device__: allocation-free) ----
__device__ float g_xt[C_DIM * B_DIM * I_DIM];     // x transposed: [c][b][i]
__device__ float g_spart[NBLK * B_DIM * UD];      // per-block s partials
__device__ float g_v[B_DIM * UD];                 // squashed v
__device__ float g_b[C_DIM * U_DIM];              // routing logits

__device__ __forceinline__ u64 mul2(u64 a, u64 b) {
    u64 r; asm("mul.rn.f32x2 %0, %1, %2;" : "=l"(r) : "l"(a), "l"(b)); return r;
}
__device__ __forceinline__ u64 fma2(u64 a, u64 b, u64 c) {
    u64 r; asm("fma.rn.f32x2 %0, %1, %2, %3;" : "=l"(r) : "l"(a), "l"(b), "l"(c)); return r;
}
__device__ __forceinline__ float hadd2(u64 a) {
    float lo, hi; asm("mov.b64 {%0,%1}, %2;" : "=f"(lo), "=f"(hi) : "l"(a));
    return lo + hi;
}
__device__ __forceinline__ float ldg_f(const float* p) {
    float r; asm volatile("ld.global.nc.f32 %0, [%1];" : "=f"(r) : "l"(p)); return r;
}
__device__ __forceinline__ u32 smem_u32(const void* p) {
    return (u32)__cvta_generic_to_shared(p);
}
__device__ __forceinline__ void cp16(u32 dst, const void* src) {
    asm volatile("cp.async.cg.shared.global [%0], [%1], 16;" :: "r"(dst), "l"(src));
}
#define CP_COMMIT() asm volatile("cp.async.commit_group;")
#define CP_WAIT0()  asm volatile("cp.async.wait_group 0;" ::: "memory")
// W row load from smem (non-volatile: may issue early)
__device__ __forceinline__ void lds_2u64(u32 a, u64& x, u64& y) {
    asm("ld.shared.v2.u64 {%0,%1}, [%2];" : "=l"(x), "=l"(y) : "r"(a));
}
// x load from smem (volatile: stop hoist-all / reg bomb)
__device__ __forceinline__ void lds_2u64v(u32 a, u64& x, u64& y) {
    asm volatile("ld.shared.v2.u64 {%0,%1}, [%2];" : "=l"(x), "=l"(y) : "r"(a));
}
__device__ __forceinline__ float dot8(u64 wa0, u64 wa1, u64 wb0, u64 wb1,
                                      u64 x0, u64 x1, u64 x2, u64 x3) {
    u64 acc = mul2(wa0, x0);
    acc = fma2(wa1, x1, acc);
    acc = fma2(wb0, x2, acc);
    acc = fma2(wb1, x3, acc);
    return hadd2(acc);
}

// x (B,I,C) -> g_xt[c][b][i]
__global__ void k_transpose(const float* __restrict__ x) {
    int idx = blockIdx.x * blockDim.x + threadIdx.x;
    if (idx >= C_DIM * B_DIM * I_DIM) return;
    int c = idx >> 9;
    int r = idx & 511;
    int b = r >> 3;
    int i = r & 7;
    g_xt[idx] = x[(b * I_DIM + i) * C_DIM + c];
}

// ---------------------------------------------------------------------------
// Fused routing pass, cp.async software-pipelined.
// 32 warps = 16 ud-groups (wu) x 2 b-groups (wb).
// Lane owns ud = wu*32 + lane (u = wu*2 + (lane>>4), d = lane&15),
// batches b = wb*32 + 0..31.  sacc[32] regs, W row = 8 regs -> ~60 regs total.
// W_c (16KB) + x_c (2KB) staged in smem one c ahead (double-buffered).
// PASS>0: stash u_hat as packed half (uint4 STS/LDS.128), softmax redundant
// per warp off ping-pong red_sm; ONE barrier per c (= pipeline boundary).
// ---------------------------------------------------------------------------
template <int PASS>
__global__ void __launch_bounds__(NTH, 1) k_pass(const float* __restrict__ W) {
    extern __shared__ char dyn[];
    // layout: Wbuf[2][16384] | xbuf[2][2048] | stash[65536 (PASS>0)]
    const u32 wbase  = smem_u32(dyn);
    const u32 xbase  = wbase + 32768;
    const u32 stbase = xbase + 4096;
    __shared__ float red_sm[2][2][32];

    const int tid  = threadIdx.x;
    const int w    = tid >> 5;
    const int lane = tid & 31;
    const int wu   = w & 15;
    const int wb   = w >> 4;
    const int hw   = lane >> 4;
    const int ud   = wu * 32 + lane;

    float sacc[32];
#pragma unroll
    for (int r = 0; r < 32; r++) sacc[r] = 0.f;

    const int cbeg = (blockIdx.x * C_DIM) / NBLK;
    const int cend = ((blockIdx.x + 1) * C_DIM) / NBLK;
    int par = 0;

    // prologue: stage first c
    cp16(wbase + tid * 16, (const char*)(W + (size_t)cbeg * 4096) + tid * 16);
    if (tid < 128)
        cp16(xbase + tid * 16, (const char*)(g_xt + cbeg * 512) + tid * 16);
    CP_COMMIT();
    CP_WAIT0();
    __syncthreads();

    for (int c = cbeg; c < cend; c++) {
        // issue next c's staging into the other buffer (overlaps phase A)
        if (c + 1 < cend) {
            const int np = par ^ 1;
            cp16(wbase + np * 16384 + tid * 16,
                 (const char*)(W + (size_t)(c + 1) * 4096) + tid * 16);
            if (tid < 128)
                cp16(xbase + np * 2048 + tid * 16,
                     (const char*)(g_xt + (c + 1) * 512) + tid * 16);
        }
        CP_COMMIT();

        // this lane's W row (8 floats) from smem
        u64 wa0, wa1, wbb0, wbb1;
        lds_2u64(wbase + par * 16384 + ud * 32, wa0, wa1);
        lds_2u64(wbase + par * 16384 + ud * 32 + 16, wbb0, wbb1);

        float bprev = (PASS == 2) ? g_b[c * U_DIM + lane] : 0.f;
        const float* vb = g_v + (wb * 32) * UD + ud;
        const u32 xb = xbase + par * 2048 + wb * 1024;
        float dp = 0.f;

#pragma unroll
        for (int j = 0; j < 4; j++) {           // 8 batches per chunk
            u32 pk[4];
#pragma unroll
            for (int t2 = 0; t2 < 4; t2++) {    // 2 batches per step
                const int r = j * 8 + t2 * 2;
                u64 x0, x1, x2, x3, y0, y1, y2, y3;
                lds_2u64v(xb + r * 32,      x0, x1);
                lds_2u64v(xb + r * 32 + 16, x2, x3);
                lds_2u64v(xb + r * 32 + 32, y0, y1);
                lds_2u64v(xb + r * 32 + 48, y2, y3);
                float ua = dot8(wa0, wa1, wbb0, wbb1, x0, x1, x2, x3);
                float ub = dot8(wa0, wa1, wbb0, wbb1, y0, y1, y2, y3);
                if (PASS > 0) {
                    dp = fmaf(ua, ldg_f(vb + r * UD), dp);
                    dp = fmaf(ub, ldg_f(vb + (r + 1) * UD), dp);
                    __half2 h2 = __floats2half2_rn(ua, ub);
                    pk[t2] = *(u32*)&h2;
                } else {
                    sacc[r]     += ua;
                    sacc[r + 1] += ub;
                }
            }
            if (PASS > 0) {
                asm volatile("st.shared.v4.b32 [%0], {%1,%2,%3,%4};"
                             :: "r"(stbase + (j * NTH + tid) * 16),
                                "r"(pk[0]), "r"(pk[1]), "r"(pk[2]), "r"(pk[3]));
            }
        }

        if (PASS > 0) {
            // reduce dp over d (16-lane segments); lanes 0/16 hold u partials
#pragma unroll
            for (int off = 8; off; off >>= 1)
                dp += __shfl_down_sync(0xffffffffu, dp, off, 16);
            if ((lane & 15) == 0)
                red_sm[par][wb][wu * 2 + hw] = dp;
        }

        CP_WAIT0();                 // next c's operands landed
        __syncthreads();            // the ONLY barrier this c

        if (PASS > 0) {
            // redundant per-warp softmax over u (lane = u)
            float dv = red_sm[par][0][lane] + red_sm[par][1][lane];
            float bv = dv * (1.0f / 64.0f) + bprev;
            if (PASS == 1 && w == 0) g_b[c * U_DIM + lane] = bv;
            float m = bv;
#pragma unroll
            for (int off = 16; off; off >>= 1)
                m = fmaxf(m, __shfl_xor_sync(0xffffffffu, m, off));
            float e = __expf(bv - m);
            float ssum = e;
#pragma unroll
            for (int off = 16; off; off >>= 1)
                ssum += __shfl_xor_sync(0xffffffffu, ssum, off);
            float cij = __shfl_sync(0xffffffffu, e / ssum, wu * 2 + hw);

            // phase B: accumulate s from stash (self-written, no extra sync)
#pragma unroll
            for (int j = 0; j < 4; j++) {
                u32 q0, q1, q2, q3;
                asm volatile("ld.shared.v4.b32 {%0,%1,%2,%3}, [%4];"
                             : "=r"(q0), "=r"(q1), "=r"(q2), "=r"(q3)
                             : "r"(stbase + (j * NTH + tid) * 16));
                u32 qs[4] = {q0, q1, q2, q3};
#pragma unroll
                for (int t2 = 0; t2 < 4; t2++) {
                    float2 uv = __half22float2(*(__half2*)&qs[t2]);
                    sacc[j * 8 + t2 * 2]     = fmaf(cij, uv.x, sacc[j * 8 + t2 * 2]);
                    sacc[j * 8 + t2 * 2 + 1] = fmaf(cij, uv.y, sacc[j * 8 + t2 * 2 + 1]);
                }
            }
        }
        par ^= 1;
    }

    const float scale = (PASS == 0) ? (1.0f / 32.0f) : 1.0f;
    float* sp = g_spart + (size_t)blockIdx.x * (B_DIM * UD) + ud;
#pragma unroll
    for (int r = 0; r < 32; r++)
        sp[(wb * 32 + r) * UD] = sacc[r] * scale;
}

// Reduce per-block s partials, apply squash (mag over U axis — reference quirk).
__global__ void k_redsquash(float* __restrict__ dout, int final_out) {
    __shared__ float sq_sm[UD];
    __shared__ float r_sm[D_DIM];
    int b = blockIdx.x;
    int ud = threadIdx.x;      // 512 threads
    float val = 0.f;
    const float* sp = g_spart + b * UD + ud;
#pragma unroll 4
    for (int p = 0; p < NBLK; p++) val += sp[(size_t)p * (B_DIM * UD)];
    sq_sm[ud] = val * val;
    __syncthreads();
    if (ud < D_DIM) {
        float msq = 0.f;
#pragma unroll
        for (int u = 0; u < U_DIM; u++) msq += sq_sm[u * D_DIM + ud];
        r_sm[ud] = sqrtf(msq) / (1.0f + msq);   // mag_sq/((1+mag_sq)*mag)
    }
    __syncthreads();
    float v = val * r_sm[ud & 15];
    float* dst = final_out ? dout : g_v;
    dst[b * UD + ud] = v;
}

extern "C" void kernel_launch(void* const* d_in, const int* in_sizes, int n_in,
                              void* d_out, int out_size) {
    const float* x = (const float*)d_in[0];
    const float* W = (const float*)d_in[1];
    if (n_in >= 2 && in_sizes[0] == C_DIM * U_DIM * D_DIM * I_DIM) {
        const float* t = x; x = W; W = t;
    }
    float* out = (float*)d_out;

    const int SM0 = 32768 + 4096;            // W/x buffers only
    const int SM1 = 32768 + 4096 + 65536;    // + stash
    cudaFuncSetAttribute(k_pass<0>, cudaFuncAttributeMaxDynamicSharedMemorySize, SM0);
    cudaFuncSetAttribute(k_pass<1>, cudaFuncAttributeMaxDynamicSharedMemorySize, SM1);
    cudaFuncSetAttribute(k_pass<2>, cudaFuncAttributeMaxDynamicSharedMemorySize, SM1);

    k_transpose<<<(C_DIM * B_DIM * I_DIM + 255) / 256, 256>>>(x);

    // iteration 1: uniform cij -> s1 -> v1
    k_pass<0><<<NBLK, NTH, SM0>>>(W);
    k_redsquash<<<B_DIM, UD>>>(out, 0);

    // iteration 2: delta(v1), b = delta, softmax -> s2 -> v2
    k_pass<1><<<NBLK, NTH, SM1>>>(W);
    k_redsquash<<<B_DIM, UD>>>(out, 0);

    // iteration 3: delta(v2), b += delta, softmax -> s3 -> v3 (output)
    k_pass<2><<<NBLK, NTH, SM1>>>(W);
    k_redsquash<<<B_DIM, UD>>>(out, 1);
}

// round 9
// speedup vs baseline: 1.7396x; 1.1192x over previous
#include <cuda_runtime.h>
#include <cuda_fp16.h>

#define C_DIM 2048
#define B_DIM 64
#define I_DIM 8
#define U_DIM 32
#define D_DIM 16
#define UD    512
#define NBLK  148
#define NTH   1024

typedef unsigned long long u64;
typedef unsigned int u32;

// ---- scratch (static __device__: allocation-free) ----
__device__ float g_xt[C_DIM * B_DIM * I_DIM];     // x transposed: [c][b][i]
__device__ float g_spart[NBLK * B_DIM * UD];      // per-block s partials
__device__ u32   g_vh[(B_DIM / 2) * UD];          // v as half2 pairs: [b/2][ud]
__device__ float g_b[C_DIM * U_DIM];              // routing logits

__device__ __forceinline__ u64 mul2(u64 a, u64 b) {
    u64 r; asm("mul.rn.f32x2 %0, %1, %2;" : "=l"(r) : "l"(a), "l"(b)); return r;
}
__device__ __forceinline__ u64 fma2(u64 a, u64 b, u64 c) {
    u64 r; asm("fma.rn.f32x2 %0, %1, %2, %3;" : "=l"(r) : "l"(a), "l"(b), "l"(c)); return r;
}
__device__ __forceinline__ float hadd2(u64 a) {
    float lo, hi; asm("mov.b64 {%0,%1}, %2;" : "=f"(lo), "=f"(hi) : "l"(a));
    return lo + hi;
}
__device__ __forceinline__ u32 ldg_u32(const u32* p) {
    u32 r; asm volatile("ld.global.nc.b32 %0, [%1];" : "=r"(r) : "l"(p)); return r;
}
__device__ __forceinline__ u32 smem_u32(const void* p) {
    return (u32)__cvta_generic_to_shared(p);
}
__device__ __forceinline__ void cp16(u32 dst, const void* src) {
    asm volatile("cp.async.cg.shared.global [%0], [%1], 16;" :: "r"(dst), "l"(src));
}
#define CP_COMMIT() asm volatile("cp.async.commit_group;")
#define CP_WAIT0()  asm volatile("cp.async.wait_group 0;" ::: "memory")
__device__ __forceinline__ void lds_2u64(u32 a, u64& x, u64& y) {
    asm("ld.shared.v2.u64 {%0,%1}, [%2];" : "=l"(x), "=l"(y) : "r"(a));
}
__device__ __forceinline__ void lds_2u64v(u32 a, u64& x, u64& y) {
    asm volatile("ld.shared.v2.u64 {%0,%1}, [%2];" : "=l"(x), "=l"(y) : "r"(a));
}
__device__ __forceinline__ float dot8(u64 wa0, u64 wa1, u64 wb0, u64 wb1,
                                      u64 x0, u64 x1, u64 x2, u64 x3) {
    u64 acc = mul2(wa0, x0);
    acc = fma2(wa1, x1, acc);
    acc = fma2(wb0, x2, acc);
    acc = fma2(wb1, x3, acc);
    return hadd2(acc);
}

// x (B,I,C) -> g_xt[c][b][i]
__global__ void k_transpose(const float* __restrict__ x) {
    int idx = blockIdx.x * blockDim.x + threadIdx.x;
    if (idx >= C_DIM * B_DIM * I_DIM) return;
    int c = idx >> 9;
    int r = idx & 511;
    int b = r >> 3;
    int i = r & 7;
    g_xt[idx] = x[(b * I_DIM + i) * C_DIM + c];
}

// ---------------------------------------------------------------------------
// Fused routing pass, cp.async software-pipelined.
// 32 warps = 16 ud-groups (wu) x 2 b-groups (wb); lane owns ud = wu*32+lane,
// batches b = wb*32 + 0..31.
// W staged SWIZZLED: [ihalf][ud] 16B chunks -> conflict-free lane reads.
// v read as half2 pairs (b even/odd), stash as packed half2 x2 (STS.64).
// ---------------------------------------------------------------------------
template <int PASS>
__global__ void __launch_bounds__(NTH, 1) k_pass(const float* __restrict__ W) {
    extern __shared__ char dyn[];
    // layout: Wbuf[2][16384] | xbuf[2][2048] | stash[65536 (PASS>0)]
    const u32 wbase  = smem_u32(dyn);
    const u32 xbase  = wbase + 32768;
    const u32 stbase = xbase + 4096;
    __shared__ float red_sm[2][2][32];

    const int tid  = threadIdx.x;
    const int w    = tid >> 5;
    const int lane = tid & 31;
    const int wu   = w & 15;
    const int wb   = w >> 4;
    const int hw   = lane >> 4;
    const int ud   = wu * 32 + lane;

    // swizzled W staging dst for this thread's chunk (tid = ud*2 + ihalf)
    const u32 wdst = (u32)((tid & 1) * 8192 + (tid >> 1) * 16);

    float sacc[32];
#pragma unroll
    for (int r = 0; r < 32; r++) sacc[r] = 0.f;

    const int cbeg = (blockIdx.x * C_DIM) / NBLK;
    const int cend = ((blockIdx.x + 1) * C_DIM) / NBLK;
    int par = 0;

    // prologue: stage first c
    cp16(wbase + wdst, (const char*)(W + (size_t)cbeg * 4096) + tid * 16);
    if (tid < 128)
        cp16(xbase + tid * 16, (const char*)(g_xt + cbeg * 512) + tid * 16);
    CP_COMMIT();
    CP_WAIT0();
    __syncthreads();

    for (int c = cbeg; c < cend; c++) {
        // issue next c's staging into the other buffer (overlaps phase A)
        if (c + 1 < cend) {
            const int np = par ^ 1;
            cp16(wbase + np * 16384 + wdst,
                 (const char*)(W + (size_t)(c + 1) * 4096) + tid * 16);
            if (tid < 128)
                cp16(xbase + np * 2048 + tid * 16,
                     (const char*)(g_xt + (c + 1) * 512) + tid * 16);
        }
        CP_COMMIT();

        // this lane's W row from swizzled smem (conflict-free 16B-stride)
        u64 wa0, wa1, wbb0, wbb1;
        lds_2u64(wbase + par * 16384 + ud * 16, wa0, wa1);
        lds_2u64(wbase + par * 16384 + 8192 + ud * 16, wbb0, wbb1);

        float bprev = (PASS == 2) ? g_b[c * U_DIM + lane] : 0.f;
        const u32* vb = g_vh + (wb * 16) * UD + ud;       // half2 per 2 batches
        const u32 xb = xbase + par * 2048 + wb * 1024;
        float dp = 0.f;

#pragma unroll
        for (int j = 0; j < 8; j++) {           // 4 batches per chunk
            u32 pk[2];
#pragma unroll
            for (int t2 = 0; t2 < 2; t2++) {    // 2 batches per step
                const int r = j * 4 + t2 * 2;
                u64 x0, x1, x2, x3, y0, y1, y2, y3;
                lds_2u64v(xb + r * 32,      x0, x1);
                lds_2u64v(xb + r * 32 + 16, x2, x3);
                lds_2u64v(xb + r * 32 + 32, y0, y1);
                lds_2u64v(xb + r * 32 + 48, y2, y3);
                float ua = dot8(wa0, wa1, wbb0, wbb1, x0, x1, x2, x3);
                float ub = dot8(wa0, wa1, wbb0, wbb1, y0, y1, y2, y3);
                if (PASS > 0) {
                    u32 vh = ldg_u32(vb + (r >> 1) * UD);        // coalesced
                    float2 vv = __half22float2(*(__half2*)&vh);
                    dp = fmaf(ua, vv.x, dp);
                    dp = fmaf(ub, vv.y, dp);
                    __half2 h2 = __floats2half2_rn(ua, ub);
                    pk[t2] = *(u32*)&h2;
                } else {
                    sacc[r]     += ua;
                    sacc[r + 1] += ub;
                }
            }
            if (PASS > 0) {
                asm volatile("st.shared.v2.b32 [%0], {%1,%2};"
                             :: "r"(stbase + (j * NTH + tid) * 8),
                                "r"(pk[0]), "r"(pk[1]));
            }
        }

        if (PASS > 0) {
            // reduce dp over d (16-lane segments); lanes 0/16 hold u partials
#pragma unroll
            for (int off = 8; off; off >>= 1)
                dp += __shfl_down_sync(0xffffffffu, dp, off, 16);
            if ((lane & 15) == 0)
                red_sm[par][wb][wu * 2 + hw] = dp;
        }

        CP_WAIT0();                 // next c's operands landed
        __syncthreads();            // the ONLY barrier this c

        if (PASS > 0) {
            // redundant per-warp softmax over u (lane = u)
            float dv = red_sm[par][0][lane] + red_sm[par][1][lane];
            float bv = dv * (1.0f / 64.0f) + bprev;
            if (PASS == 1 && w == 0) g_b[c * U_DIM + lane] = bv;
            float m = bv;
#pragma unroll
            for (int off = 16; off; off >>= 1)
                m = fmaxf(m, __shfl_xor_sync(0xffffffffu, m, off));
            float e = __expf(bv - m);
            float ssum = e;
#pragma unroll
            for (int off = 16; off; off >>= 1)
                ssum += __shfl_xor_sync(0xffffffffu, ssum, off);
            float cij = __shfl_sync(0xffffffffu, e / ssum, wu * 2 + hw);

            // phase B: accumulate s from stash (self-written, no extra sync)
#pragma unroll
            for (int j = 0; j < 8; j++) {
                u32 q0, q1;
                asm volatile("ld.shared.v2.b32 {%0,%1}, [%2];"
                             : "=r"(q0), "=r"(q1)
                             : "r"(stbase + (j * NTH + tid) * 8));
                float2 a = __half22float2(*(__half2*)&q0);
                float2 bq = __half22float2(*(__half2*)&q1);
                sacc[j * 4]     = fmaf(cij, a.x,  sacc[j * 4]);
                sacc[j * 4 + 1] = fmaf(cij, a.y,  sacc[j * 4 + 1]);
                sacc[j * 4 + 2] = fmaf(cij, bq.x, sacc[j * 4 + 2]);
                sacc[j * 4 + 3] = fmaf(cij, bq.y, sacc[j * 4 + 3]);
            }
        }
        par ^= 1;
    }

    const float scale = (PASS == 0) ? (1.0f / 32.0f) : 1.0f;
    float* sp = g_spart + (size_t)blockIdx.x * (B_DIM * UD) + ud;
#pragma unroll
    for (int r = 0; r < 32; r++)
        sp[(wb * 32 + r) * UD] = sacc[r] * scale;
}

// Reduce per-block s partials, apply squash (mag over U axis — reference quirk).
// 1024 threads: two partial-halves per ud, then combine.
__global__ void k_redsquash(float* __restrict__ dout, int final_out) {
    __shared__ float part[UD];
    __shared__ float sq_sm[UD];
    __shared__ float r_sm[D_DIM];
    const int b  = blockIdx.x;
    const int ud = threadIdx.x & 511;
    const int ph = threadIdx.x >> 9;
    float val = 0.f;
    const float* sp = g_spart + b * UD + ud;
    const int p0 = ph * 74;
#pragma unroll 4
    for (int p = p0; p < p0 + 74; p++) val += sp[(size_t)p * (B_DIM * UD)];
    if (ph) part[ud] = val;
    __syncthreads();
    if (!ph) {
        val += part[ud];
        sq_sm[ud] = val * val;
    }
    __syncthreads();
    if (threadIdx.x < D_DIM) {
        float msq = 0.f;
#pragma unroll
        for (int u = 0; u < U_DIM; u++) msq += sq_sm[u * D_DIM + threadIdx.x];
        r_sm[threadIdx.x] = sqrtf(msq) / (1.0f + msq);   // mag_sq/((1+mag_sq)*mag)
    }
    __syncthreads();
    if (!ph) {
        float v = val * r_sm[ud & 15];
        if (final_out) {
            dout[b * UD + ud] = v;
        } else {
            // store v as half into paired layout g_vh[b/2][ud] (lo=even b, hi=odd b)
            ((__half*)g_vh)[(b >> 1) * (UD * 2) + ud * 2 + (b & 1)] = __float2half_rn(v);
        }
    }
}

extern "C" void kernel_launch(void* const* d_in, const int* in_sizes, int n_in,
                              void* d_out, int out_size) {
    const float* x = (const float*)d_in[0];
    const float* W = (const float*)d_in[1];
    if (n_in >= 2 && in_sizes[0] == C_DIM * U_DIM * D_DIM * I_DIM) {
        const float* t = x; x = W; W = t;
    }
    float* out = (float*)d_out;

    const int SM0 = 32768 + 4096;            // W/x buffers only
    const int SM1 = 32768 + 4096 + 65536;    // + stash
    cudaFuncSetAttribute(k_pass<0>, cudaFuncAttributeMaxDynamicSharedMemorySize, SM0);
    cudaFuncSetAttribute(k_pass<1>, cudaFuncAttributeMaxDynamicSharedMemorySize, SM1);
    cudaFuncSetAttribute(k_pass<2>, cudaFuncAttributeMaxDynamicSharedMemorySize, SM1);

    k_transpose<<<(C_DIM * B_DIM * I_DIM + 255) / 256, 256>>>(x);

    // iteration 1: uniform cij -> s1 -> v1
    k_pass<0><<<NBLK, NTH, SM0>>>(W);
    k_redsquash<<<B_DIM, NTH>>>(out, 0);

    // iteration 2: delta(v1), b = delta, softmax -> s2 -> v2
    k_pass<1><<<NBLK, NTH, SM1>>>(W);
    k_redsquash<<<B_DIM, NTH>>>(out, 0);

    // iteration 3: delta(v2), b += delta, softmax -> s3 -> v3 (output)
    k_pass<2><<<NBLK, NTH, SM1>>>(W);
    k_redsquash<<<B_DIM, NTH>>>(out, 1);
}